// round 2
// baseline (speedup 1.0000x reference)
#include <cuda_runtime.h>
#include <cuda_bf16.h>

// FocalLossAdaptive: input [N=8192, C=32000] fp32, target [N] int (32- or 64-bit) -> scalar mean loss.
// Single-pass online softmax per row (one CTA per row), then deterministic reduce.

#define NROWS 8192
#define NCOLS 32000
#define NVEC  (NCOLS / 4)   // 8000 float4 per row
#define TPB   256

__device__ float g_row_loss[NROWS];

// Targets may be serialized as int32 or little-endian int64. Probe: if int64,
// the odd 32-bit words (high halves of values < 32000) are all zero.
__device__ __forceinline__ int load_target(const int* __restrict__ t32, int row) {
    bool is64 = true;
    #pragma unroll
    for (int i = 0; i < 16; i++) is64 &= (t32[2 * i + 1] == 0);
    int t = is64 ? t32[2 * row] : t32[row];
    // clamp defensively; never produce an OOB gather
    return (t < 0) ? 0 : (t >= NCOLS ? NCOLS - 1 : t);
}

__global__ __launch_bounds__(TPB) void focal_rows_kernel(const float* __restrict__ inp,
                                                         const int* __restrict__ tgt) {
    const int row = blockIdx.x;
    const float* __restrict__ p = inp + (size_t)row * NCOLS;
    const float4* __restrict__ p4 = (const float4*)p;
    const int tid = threadIdx.x;

    // Per-thread online logsumexp state
    float m = -1e30f;
    float s = 0.0f;

    for (int i = tid; i < NVEC; i += TPB) {
        float4 v = p4[i];
        float m4 = fmaxf(fmaxf(v.x, v.y), fmaxf(v.z, v.w));
        if (m4 <= m) {
            // common path after warmup: 4 exps, no rescale
            s += __expf(v.x - m) + __expf(v.y - m) + __expf(v.z - m) + __expf(v.w - m);
        } else {
            // rare: new running max -> rescale accumulator once
            s = s * __expf(m - m4);
            s += __expf(v.x - m4) + __expf(v.y - m4) + __expf(v.z - m4) + __expf(v.w - m4);
            m = m4;
        }
    }

    // Warp-level combine of (m, s) pairs
    #pragma unroll
    for (int k = 16; k > 0; k >>= 1) {
        float om = __shfl_xor_sync(0xffffffffu, m, k);
        float os = __shfl_xor_sync(0xffffffffu, s, k);
        float M  = fmaxf(m, om);
        s = s * __expf(m - M) + os * __expf(om - M);
        m = M;
    }

    __shared__ float shm[TPB / 32];
    __shared__ float shs[TPB / 32];
    const int warp = tid >> 5;
    const int lane = tid & 31;
    if (lane == 0) { shm[warp] = m; shs[warp] = s; }
    __syncthreads();

    if (tid == 0) {
        float M = shm[0];
        float S = shs[0];
        #pragma unroll
        for (int w = 1; w < TPB / 32; w++) {
            float om = shm[w], os = shs[w];
            float Mn = fmaxf(M, om);
            S = S * __expf(M - Mn) + os * __expf(om - Mn);
            M = Mn;
        }
        int t = load_target(tgt, row);
        float xt = p[t];
        float logpt = xt - M - logf(S);     // accurate log on the scalar path
        float pt = __expf(logpt);
        float u  = 1.0f - pt;
        float u3 = u * u * u;
        // gamma: pt >= 0.5 -> 3 ; pt < 0.2 -> 5 ; 0.2 <= pt < 0.5 -> 3  => 5 iff pt < 0.2
        float w_ = (pt < 0.2f) ? u3 * u * u : u3;
        g_row_loss[row] = -w_ * logpt;
    }
}

__global__ __launch_bounds__(TPB) void reduce_mean_kernel(float* __restrict__ out) {
    __shared__ float sh[TPB];
    float a = 0.0f;
    for (int i = threadIdx.x; i < NROWS; i += TPB) a += g_row_loss[i];
    sh[threadIdx.x] = a;
    __syncthreads();
    #pragma unroll
    for (int k = TPB / 2; k > 0; k >>= 1) {
        if (threadIdx.x < k) sh[threadIdx.x] += sh[threadIdx.x + k];
        __syncthreads();
    }
    if (threadIdx.x == 0) out[0] = sh[0] * (1.0f / (float)NROWS);
}

extern "C" void kernel_launch(void* const* d_in, const int* in_sizes, int n_in,
                              void* d_out, int out_size) {
    const float* inp = (const float*)d_in[0];
    const int*   tgt = (const int*)d_in[1];
    float*       out = (float*)d_out;

    focal_rows_kernel<<<NROWS, TPB>>>(inp, tgt);
    reduce_mean_kernel<<<1, TPB>>>(out);
}